// round 1
// baseline (speedup 1.0000x reference)
#include <cuda_runtime.h>

#define BB 2048
#define TT 128
#define NN 64
#define HH 128
#define G4 512   // 4*H
#define MM 8     // batches per CTA

// ---------------- device scratch (allocation-free: __device__ globals) -------
__device__ __align__(16) float g_prex[BB * NN * HH];   // [b][n][k]  67 MB
__device__ __align__(16) float g_WhsT[256 * HH];       // [j][k]   j<128: W1_h col, j>=128: W1_s col
__device__ __align__(16) float g_W1xT[TT * HH];        // [t][k]
__device__ __align__(16) float g_WihG[NN * G4];        // [n][q*4+gate]
__device__ __align__(16) float g_WhhG[HH * G4];        // [j][q*4+gate]
__device__ __align__(16) float g_bG[G4];               // [q*4+gate]

__device__ __forceinline__ float tanh_fast(float x) {
    float y; asm("tanh.approx.f32 %0, %1;" : "=f"(y) : "f"(x)); return y;
}
__device__ __forceinline__ float sigmoid_f(float x) {
    return 1.0f / (1.0f + __expf(-x));
}
__device__ __forceinline__ void fma4(float4& a, float s, const float4 w) {
    a.x = fmaf(s, w.x, a.x); a.y = fmaf(s, w.y, a.y);
    a.z = fmaf(s, w.z, a.z); a.w = fmaf(s, w.w, a.w);
}

// ---------------- kernel 0: weight layout prep --------------------------------
__global__ void prep_kernel(const float* __restrict__ W_attn1,
                            const float* __restrict__ W_ih,
                            const float* __restrict__ W_hh,
                            const float* __restrict__ b_ih,
                            const float* __restrict__ b_hh)
{
    int tid = blockIdx.x * blockDim.x + threadIdx.x;
    int nt  = gridDim.x * blockDim.x;
    // WhsT[j*128+k] = W_attn1[k*384 + j]   (covers both W1_h (j<128) and W1_s (j in [128,256)))
    for (int i = tid; i < 256 * HH; i += nt) {
        int j = i >> 7, k = i & 127;
        g_WhsT[i] = W_attn1[k * 384 + j];
    }
    // W1xT[t*128+k] = W_attn1[k*384 + 256 + t]
    for (int i = tid; i < TT * HH; i += nt) {
        int t = i >> 7, k = i & 127;
        g_W1xT[i] = W_attn1[k * 384 + 256 + t];
    }
    // WihG[n*512 + q*4+g] = W_ih[(g*128+q)*64 + n]
    for (int i = tid; i < NN * G4; i += nt) {
        int n = i >> 9, r = i & 511, q = r >> 2, g = r & 3;
        g_WihG[i] = W_ih[(g * HH + q) * NN + n];
    }
    // WhhG[j*512 + q*4+g] = W_hh[(g*128+q)*128 + j]
    for (int i = tid; i < HH * G4; i += nt) {
        int j = i >> 9, r = i & 511, q = r >> 2, g = r & 3;
        g_WhhG[i] = W_hh[(g * HH + q) * HH + j];
    }
    for (int i = tid; i < G4; i += nt) {
        int q = i >> 2, g = i & 3;
        g_bG[i] = b_ih[g * HH + q] + b_hh[g * HH + q];
    }
}

// ---------------- kernel 1: pre_x[b][n][k] = sum_t X[b][t][n]*W1x[k][t] + b1[k]
__global__ __launch_bounds__(256) void prex_kernel(const float* __restrict__ X,
                                                   const float* __restrict__ b_attn1)
{
    __shared__ float sX[TT * NN];   // [t][n]  32 KB
    int b = blockIdx.x;
    int tid = threadIdx.x;
    const float* Xb = X + (size_t)b * TT * NN;
    for (int i = tid; i < TT * NN; i += 256) sX[i] = Xb[i];
    __syncthreads();

    const float4* W4  = (const float4*)g_W1xT;     // [t][32 quads]
    const float4* b14 = (const float4*)b_attn1;
    float4* out4 = (float4*)(g_prex + (size_t)b * NN * HH);

    for (int qi = tid; qi < NN * 32; qi += 256) {
        int n = qi >> 5, kq = qi & 31;
        float4 acc = b14[kq];
        #pragma unroll 4
        for (int t = 0; t < TT; ++t) {
            float x = sX[t * NN + n];
            fma4(acc, x, W4[t * 32 + kq]);
        }
        out4[n * 32 + kq] = acc;
    }
}

// ---------------- kernel 2: the recurrence ------------------------------------
__global__ __launch_bounds__(256, 2) void rnn_kernel(
    const float* __restrict__ X,
    const float* __restrict__ w_attn2,
    const float* __restrict__ b_attn2,
    float* __restrict__ out)
{
    __shared__ __align__(16) float s_hc[MM][256];  // [m][0:128]=h, [128:256]=c
    __shared__ __align__(16) float s_u [MM][HH];
    __shared__ float s_e [MM][NN];
    __shared__ float s_xt[MM][NN];

    int tid  = threadIdx.x;
    int lane = tid & 31;
    int warp = tid >> 5;            // warp == m for phases (a)(b)(c)
    int b0   = blockIdx.x * MM;

    float  b2  = b_attn2[0];
    float4 w2v = ((const float4*)w_attn2)[lane];   // k = lane*4..+3

    // zero initial state
    for (int i = tid; i < MM * 256; i += 256) ((float*)s_hc)[i] = 0.0f;

    // thread mapping for gates/update
    int q = tid & 127, grp = tid >> 7;
    int mb = grp * 4;
    const float4* WhsT4 = (const float4*)g_WhsT;   // [j][32]
    const float4* WhhG4 = (const float4*)g_WhhG;   // [j][128]
    const float4* WihG4 = (const float4*)g_WihG;   // [n][128]
    const float4* prex4 = (const float4*)g_prex;
    float4 bg = ((const float4*)g_bG)[q];
    __syncthreads();

    for (int t = 0; t < TT; ++t) {
        // ---- (a) u[m][k] = sum_j [h|c][m][j] * WhsT[j][k] ; warp=m, k=lane*4..+3
        {
            int m = warp;
            float4 acc = make_float4(0.f, 0.f, 0.f, 0.f);
            #pragma unroll 4
            for (int j = 0; j < 256; ++j) {
                float sj = s_hc[m][j];                  // broadcast
                fma4(acc, sj, WhsT4[j * 32 + lane]);    // coalesced, L1-hot
            }
            ((float4*)s_u[m])[lane] = acc;
        }
        __syncthreads();

        // ---- (b) e[m][n] = b2 + sum_k w2[k]*tanh(prex[m][n][k] + u[m][k])
        {
            int m = warp;
            float4 uv = ((const float4*)s_u[m])[lane];
            const float4* pr = prex4 + (size_t)(b0 + m) * NN * 32;
            #pragma unroll 2
            for (int n = 0; n < NN; ++n) {
                float4 p = pr[n * 32 + lane];           // coalesced 512B/warp
                float z0 = tanh_fast(p.x + uv.x);
                float z1 = tanh_fast(p.y + uv.y);
                float z2 = tanh_fast(p.z + uv.z);
                float z3 = tanh_fast(p.w + uv.w);
                float part = z0 * w2v.x + z1 * w2v.y + z2 * w2v.z + z3 * w2v.w;
                #pragma unroll
                for (int off = 16; off > 0; off >>= 1)
                    part += __shfl_xor_sync(0xffffffffu, part, off);
                if (lane == 0) s_e[m][n] = part + b2;
            }
        }
        __syncthreads();

        // ---- (c) softmax over n (64) + x_tilde ; warp=m, 2 n per lane
        {
            int m = warp;
            float e0 = s_e[m][lane], e1 = s_e[m][lane + 32];
            float mx = fmaxf(e0, e1);
            #pragma unroll
            for (int off = 16; off > 0; off >>= 1)
                mx = fmaxf(mx, __shfl_xor_sync(0xffffffffu, mx, off));
            float x0 = __expf(e0 - mx), x1 = __expf(e1 - mx);
            float sum = x0 + x1;
            #pragma unroll
            for (int off = 16; off > 0; off >>= 1)
                sum += __shfl_xor_sync(0xffffffffu, sum, off);
            float inv = 1.0f / sum;
            const float* Xr = X + ((size_t)(b0 + m) * TT + t) * NN;
            s_xt[m][lane]      = x0 * inv * Xr[lane];
            s_xt[m][lane + 32] = x1 * inv * Xr[lane + 32];
        }
        __syncthreads();

        // ---- (d) gates[m][{i,f,g,o} at q] for m = mb..mb+3
        float4 acc0 = bg, acc1 = bg, acc2 = bg, acc3 = bg;
        #pragma unroll 2
        for (int j = 0; j < HH; ++j) {
            float4 w = WhhG4[j * 128 + q];              // coalesced, shared by both grps
            float h0 = s_hc[mb + 0][j];
            float h1 = s_hc[mb + 1][j];
            float h2 = s_hc[mb + 2][j];
            float h3 = s_hc[mb + 3][j];
            fma4(acc0, h0, w); fma4(acc1, h1, w);
            fma4(acc2, h2, w); fma4(acc3, h3, w);
        }
        #pragma unroll 2
        for (int n = 0; n < NN; ++n) {
            float4 w = WihG4[n * 128 + q];
            float x0 = s_xt[mb + 0][n];
            float x1 = s_xt[mb + 1][n];
            float x2 = s_xt[mb + 2][n];
            float x3 = s_xt[mb + 3][n];
            fma4(acc0, x0, w); fma4(acc1, x1, w);
            fma4(acc2, x2, w); fma4(acc3, x3, w);
        }

        // ---- (e) LSTM update (reads of old state done before the sync)
        float hn[4], cn[4];
        #pragma unroll
        for (int mm = 0; mm < 4; ++mm) {
            float4 a = (mm == 0) ? acc0 : (mm == 1) ? acc1 : (mm == 2) ? acc2 : acc3;
            float iv = sigmoid_f(a.x);
            float fv = sigmoid_f(a.y);
            float gv = tanhf(a.z);           // accurate in the recurrent path
            float ov = sigmoid_f(a.w);
            float cold = s_hc[mb + mm][128 + q];
            float c2 = fv * cold + iv * gv;
            cn[mm] = c2;
            hn[mm] = ov * tanhf(c2);
        }
        __syncthreads();   // all reads of old h/c complete
        #pragma unroll
        for (int mm = 0; mm < 4; ++mm) {
            s_hc[mb + mm][q]       = hn[mm];
            s_hc[mb + mm][128 + q] = cn[mm];
            out[((size_t)(b0 + mb + mm) * TT + t) * HH + q] = hn[mm];
        }
        __syncthreads();   // new state visible for next step's (a)
    }
}

// ---------------- launch ------------------------------------------------------
extern "C" void kernel_launch(void* const* d_in, const int* in_sizes, int n_in,
                              void* d_out, int out_size) {
    const float* X       = (const float*)d_in[0];
    const float* W_attn1 = (const float*)d_in[1];
    const float* b_attn1 = (const float*)d_in[2];
    const float* w_attn2 = (const float*)d_in[3];
    const float* b_attn2 = (const float*)d_in[4];
    const float* W_ih    = (const float*)d_in[5];
    const float* W_hh    = (const float*)d_in[6];
    const float* b_ih    = (const float*)d_in[7];
    const float* b_hh    = (const float*)d_in[8];
    float* out = (float*)d_out;

    prep_kernel<<<64, 256>>>(W_attn1, W_ih, W_hh, b_ih, b_hh);
    prex_kernel<<<BB, 256>>>(X, b_attn1);
    rnn_kernel<<<BB / MM, 256>>>(X, w_attn2, b_attn2, out);
}